// round 1
// baseline (speedup 1.0000x reference)
#include <cuda_runtime.h>

#define DD 2048
#define PP 16000

// Sketch structure extracted from C1/C2 each launch (deterministic).
__device__ int   g_idx1[DD], g_idx2[DD];
__device__ float g_sgn1[DD], g_sgn2[DD];

// ---------------------------------------------------------------------------
// Kernel E: parse dense count-sketch matrix C [D, P] -> (idx, sign) per row.
// Bandwidth-bound: 131 MB per matrix.
// ---------------------------------------------------------------------------
__global__ void extract_kernel(const float4* __restrict__ C, int which) {
    int i4 = blockIdx.x * blockDim.x + threadIdx.x;
    const int total4 = DD * PP / 4;
    if (i4 >= total4) return;
    int*   idx = which ? g_idx2 : g_idx1;
    float* sgn = which ? g_sgn2 : g_sgn1;
    float4 v = C[i4];
    int e = i4 * 4;
    if (v.x != 0.f) { idx[e / PP]       = e % PP;       sgn[e / PP]       = v.x; }
    if (v.y != 0.f) { int q = e + 1; idx[q / PP] = q % PP; sgn[q / PP] = v.y; }
    if (v.z != 0.f) { int q = e + 2; idx[q / PP] = q % PP; sgn[q / PP] = v.z; }
    if (v.w != 0.f) { int q = e + 3; idx[q / PP] = q % PP; sgn[q / PP] = v.w; }
}

// ---------------------------------------------------------------------------
// Complex helpers
// ---------------------------------------------------------------------------
__device__ __forceinline__ float2 cadd(float2 a, float2 b) { return make_float2(a.x + b.x, a.y + b.y); }
__device__ __forceinline__ float2 csub(float2 a, float2 b) { return make_float2(a.x - b.x, a.y - b.y); }
__device__ __forceinline__ float2 cmul(float2 a, float2 b) {
    return make_float2(a.x * b.x - a.y * b.y, a.x * b.y + a.y * b.x);
}
__device__ __forceinline__ float2 cfma(float2 acc, float2 a, float2 b) {
    acc.x = fmaf(a.x, b.x, fmaf(-a.y, b.y, acc.x));
    acc.y = fmaf(a.x, b.y, fmaf(a.y, b.x, acc.y));
    return acc;
}

// 5th roots of unity: W5^k = exp(-2*pi*i*k/5)
#define W5_1 make_float2( 0.30901699437494745f, -0.9510565162951535f)
#define W5_2 make_float2(-0.8090169943749473f,  -0.5877852522924731f)
#define W5_3 make_float2(-0.8090169943749475f,   0.5877852522924730f)
#define W5_4 make_float2( 0.30901699437494723f,  0.9510565162951536f)

// ---------------------------------------------------------------------------
// Forward 2-D FFT over the 128 x 125 grid, in place in shared memory.
// Layout: Z[a * 125 + b],  a in [0,128) (radix-2 axis), b in [0,125) (radix-5).
// Natural-order in, natural-order out (explicit bit/digit reversal passes).
// ---------------------------------------------------------------------------
__device__ void fft2_forward(float2* Z, const float2* W128, const float2* W125,
                             int tid, int NT) {
    // ---- radix-2 DIF along a (7 stages) ----
#pragma unroll
    for (int m = 64; m >= 1; m >>= 1) {
        int tw = 64 / m;
        for (int q = tid; q < 125 * 64; q += NT) {
            int col = q % 125;
            int t   = q / 125;
            int j   = t % m;
            int i0  = ((t / m) * (m << 1) + j) * 125 + col;
            int i1  = i0 + m * 125;
            float2 u = Z[i0], v = Z[i1];
            Z[i0] = cadd(u, v);
            Z[i1] = cmul(csub(u, v), W128[j * tw]);
        }
        __syncthreads();
    }
    // ---- bit-reversal along a ----
    for (int q = tid; q < 16000; q += NT) {
        int a = q / 125, col = q - a * 125;
        int r = __brev((unsigned)a) >> 25;
        if (r > a) {
            int q2 = r * 125 + col;
            float2 t1 = Z[q]; Z[q] = Z[q2]; Z[q2] = t1;
        }
    }
    __syncthreads();
    // ---- radix-5 DIF along b (3 stages) ----
#pragma unroll
    for (int m = 25; m >= 1; m /= 5) {
        int twf = 25 / m;
        for (int q = tid; q < 128 * 25; q += NT) {
            int a = q & 127;
            int t = q >> 7;                 // 0..24
            int j = t % m;
            int base = a * 125 + (t / m) * (5 * m) + j;
            float2 x0 = Z[base];
            float2 x1 = Z[base + m];
            float2 x2 = Z[base + 2 * m];
            float2 x3 = Z[base + 3 * m];
            float2 x4 = Z[base + 4 * m];

            float2 y0 = cadd(cadd(cadd(cadd(x0, x1), x2), x3), x4);
            float2 y1 = x0; y1 = cfma(y1, x1, W5_1); y1 = cfma(y1, x2, W5_2); y1 = cfma(y1, x3, W5_3); y1 = cfma(y1, x4, W5_4);
            float2 y2 = x0; y2 = cfma(y2, x1, W5_2); y2 = cfma(y2, x2, W5_4); y2 = cfma(y2, x3, W5_1); y2 = cfma(y2, x4, W5_3);
            float2 y3 = x0; y3 = cfma(y3, x1, W5_3); y3 = cfma(y3, x2, W5_1); y3 = cfma(y3, x3, W5_4); y3 = cfma(y3, x4, W5_2);
            float2 y4 = x0; y4 = cfma(y4, x1, W5_4); y4 = cfma(y4, x2, W5_3); y4 = cfma(y4, x3, W5_2); y4 = cfma(y4, x4, W5_1);

            int e = j * twf;                // e < 25, so 4e <= 96 < 125
            y1 = cmul(y1, W125[e]);
            y2 = cmul(y2, W125[2 * e]);
            y3 = cmul(y3, W125[3 * e]);
            y4 = cmul(y4, W125[4 * e]);

            Z[base]         = y0;
            Z[base + m]     = y1;
            Z[base + 2 * m] = y2;
            Z[base + 3 * m] = y3;
            Z[base + 4 * m] = y4;
        }
        __syncthreads();
    }
    // ---- base-5 digit reversal along b ----
    for (int q = tid; q < 16000; q += NT) {
        int a = q / 125, b = q - a * 125;
        int d0 = b % 5, d1 = (b / 5) % 5, d2 = b / 25;
        int r = d0 * 25 + d1 * 5 + d2;
        if (r > b) {
            int q2 = a * 125 + r;
            float2 t1 = Z[q]; Z[q] = Z[q2]; Z[q2] = t1;
        }
    }
    __syncthreads();
}

// ---------------------------------------------------------------------------
// Kernel F: one CTA per batch row.
//   scatter count-sketch (y1 -> Re, y2 -> Im) onto CRT grid
//   FFT2 -> Hermitian unpack, pointwise product (store conj) -> FFT2 -> Re/N
// ---------------------------------------------------------------------------
__global__ void mcb_fft_kernel(const float* __restrict__ x1,
                               const float* __restrict__ x2,
                               float* __restrict__ out) {
    extern __shared__ float2 sm[];
    float2* Z    = sm;             // 16000
    float2* W128 = sm + 16000;     // 128
    float2* W125 = sm + 16128;     // 125

    const int tid = threadIdx.x;
    const int NT  = blockDim.x;
    const int row = blockIdx.x;

    // init: zero grid, fill twiddle tables
    for (int i = tid; i < 16000; i += NT) Z[i] = make_float2(0.f, 0.f);
    if (tid < 128) {
        float s, c;
        sincosf(-6.283185307179586f * (float)tid / 128.f, &s, &c);
        W128[tid] = make_float2(c, s);
    }
    {
        int k = tid - 128;
        if (k >= 0 && k < 125) {
            float s, c;
            sincosf(-6.283185307179586f * (float)k / 125.f, &s, &c);
            W125[k] = make_float2(c, s);
        }
    }
    __syncthreads();

    // count-sketch scatter onto CRT-mapped 2-D grid
    const float* x1r = x1 + row * DD;
    const float* x2r = x2 + row * DD;
    for (int d = tid; d < DD; d += NT) {
        int n1 = g_idx1[d];
        float v1 = g_sgn1[d] * x1r[d];
        atomicAdd(&Z[(n1 & 127) * 125 + (n1 % 125)].x, v1);
        int n2 = g_idx2[d];
        float v2 = g_sgn2[d] * x2r[d];
        atomicAdd(&Z[(n2 & 127) * 125 + (n2 % 125)].y, v2);
    }
    __syncthreads();

    // forward FFT2 of z = y1 + i*y2
    fft2_forward(Z, W128, W125, tid, NT);

    // Hermitian unpack + pointwise product; store conj(G) for inverse-via-forward
    for (int q = tid; q < 16000; q += NT) {
        int a = q / 125, b = q - a * 125;
        int mi = ((128 - a) & 127) * 125 + ((125 - b) % 125);
        if (mi < q) continue;               // one thread per {q, mi} pair
        float2 zk = Z[q], zm = Z[mi];
        float2 f1 = make_float2(0.5f * (zk.x + zm.x),  0.5f * (zk.y - zm.y));
        float2 f2 = make_float2(0.5f * (zk.y + zm.y), -0.5f * (zk.x - zm.x));
        float2 g  = cmul(f1, f2);
        Z[q]  = make_float2(g.x, -g.y);     // conj(G[q])
        Z[mi] = g;                          // conj(G[mi]) = conj(conj(G[q])) = G[q]
    }
    __syncthreads();

    // inverse FFT2 via forward on conjugated data: IFFT(G) = conj(FFT(conj G))/N
    fft2_forward(Z, W128, W125, tid, NT);

    // emit real part, CRT map back to 1-D index
    const float scale = 1.0f / 16000.0f;
    float* outr = out + row * PP;
    for (int n = tid; n < PP; n += NT) {
        outr[n] = Z[(n & 127) * 125 + (n % 125)].x * scale;
    }
}

// ---------------------------------------------------------------------------
// Launch
// ---------------------------------------------------------------------------
extern "C" void kernel_launch(void* const* d_in, const int* in_sizes, int n_in,
                              void* d_out, int out_size) {
    const float*  x1 = (const float*)d_in[0];
    const float*  x2 = (const float*)d_in[1];
    const float4* C1 = (const float4*)d_in[2];
    const float4* C2 = (const float4*)d_in[3];
    float* out = (float*)d_out;

    const int B = in_sizes[0] / DD;           // 128
    const int total4 = DD * PP / 4;
    const int eblocks = (total4 + 255) / 256; // 32000

    extract_kernel<<<eblocks, 256>>>(C1, 0);
    extract_kernel<<<eblocks, 256>>>(C2, 1);

    const size_t smem = (size_t)(16000 + 128 + 125) * sizeof(float2); // 130,024 B
    cudaFuncSetAttribute(mcb_fft_kernel,
                         cudaFuncAttributeMaxDynamicSharedMemorySize, (int)smem);
    mcb_fft_kernel<<<B, 512, smem>>>(x1, x2, out);
}

// round 2
// speedup vs baseline: 1.3961x; 1.3961x over previous
#include <cuda_runtime.h>

#define DD 2048
#define PP 16000

// Sketch structure extracted from C1/C2 each launch (deterministic).
__device__ int   g_idx1[DD], g_idx2[DD];
__device__ float g_sgn1[DD], g_sgn2[DD];

// ---------------------------------------------------------------------------
// Kernel E: parse BOTH dense count-sketch matrices [D, P] -> (idx, sign).
// Pure streaming read (262 MB); hits are rare (2048 per 8.192M int4).
// ---------------------------------------------------------------------------
__global__ void extract_kernel(const int4* __restrict__ C1,
                               const int4* __restrict__ C2) {
    int b = blockIdx.x;                      // 16000 blocks total
    const int4* C;
    int*  idx;
    float* sgn;
    int mb;
    if (b < 8000) { C = C1; idx = g_idx1; sgn = g_sgn1; mb = b; }
    else          { C = C2; idx = g_idx2; sgn = g_sgn2; mb = b - 8000; }
    int base = mb * 1024 + threadIdx.x;      // 1024 int4 per block
#pragma unroll
    for (int k = 0; k < 4; k++) {
        int i4 = base + k * 256;
        int4 v = __ldcs(&C[i4]);
        if (v.x | v.y | v.z | v.w) {
            int e = i4 * 4;
            if (v.x) { idx[e / PP] = e % PP; sgn[e / PP] = __int_as_float(v.x); }
            if (v.y) { int q = e + 1; idx[q / PP] = q % PP; sgn[q / PP] = __int_as_float(v.y); }
            if (v.z) { int q = e + 2; idx[q / PP] = q % PP; sgn[q / PP] = __int_as_float(v.z); }
            if (v.w) { int q = e + 3; idx[q / PP] = q % PP; sgn[q / PP] = __int_as_float(v.w); }
        }
    }
}

// ---------------------------------------------------------------------------
// Complex helpers
// ---------------------------------------------------------------------------
__device__ __forceinline__ float2 cadd(float2 a, float2 b) { return make_float2(a.x + b.x, a.y + b.y); }
__device__ __forceinline__ float2 csub(float2 a, float2 b) { return make_float2(a.x - b.x, a.y - b.y); }
__device__ __forceinline__ float2 cmul(float2 a, float2 b) {
    return make_float2(a.x * b.x - a.y * b.y, a.x * b.y + a.y * b.x);
}
__device__ __forceinline__ float2 cfma(float2 acc, float2 a, float2 b) {
    acc.x = fmaf(a.x, b.x, fmaf(-a.y, b.y, acc.x));
    acc.y = fmaf(a.x, b.y, fmaf(a.y, b.x, acc.y));
    return acc;
}

// 5th roots of unity: W5^k = exp(-2*pi*i*k/5)
#define W5_1 make_float2( 0.30901699437494745f, -0.9510565162951535f)
#define W5_2 make_float2(-0.8090169943749473f,  -0.5877852522924731f)
#define W5_3 make_float2(-0.8090169943749475f,   0.5877852522924730f)
#define W5_4 make_float2( 0.30901699437494723f,  0.9510565162951536f)

__device__ __constant__ int c_brev4[16] = {0,8,4,12,2,10,6,14,1,9,5,13,3,11,7,15};
__device__ __constant__ int c_brev3[8]  = {0,4,2,6,1,5,3,7};

__device__ __forceinline__ int digrev125(int b) {
    // base-5 digit reversal of 3 digits
    int d0 = b % 5, d1 = (b / 5) % 5, d2 = b / 25;
    return d0 * 25 + d1 * 5 + d2;
}

// ---------------------------------------------------------------------------
// Fused radix-2 butterfly blocks (DIF, logical t-order). Twiddles match the
// stage-by-stage radix-2 DIF of length 128 exactly.
// bfly16: stages m = 64, 32, 16, 8.  a = j + 8*t.  tw = W128[(j+8*(t&(ls-1)))*(8/ls)]
// bfly8 : stages m =  4,  2,  1.     a = 8*g + t.  tw = W128[(t&(ls-1))*(64/ls)]
// ---------------------------------------------------------------------------
__device__ __forceinline__ void bfly16(float2* X, int j, const float2* W128) {
#pragma unroll
    for (int ls = 8; ls >= 1; ls >>= 1) {
        int f = 8 / ls;
#pragma unroll
        for (int g = 0; g < 8 / ls; g++)
#pragma unroll
            for (int i = 0; i < ls; i++) {
                int t0 = g * 2 * ls + i, t1 = t0 + ls;
                float2 u = X[t0], v = X[t1];
                X[t0] = cadd(u, v);
                X[t1] = cmul(csub(u, v), W128[(j + 8 * i) * f]);
            }
    }
}

__device__ __forceinline__ void bfly8(float2* X, const float2* W128) {
#pragma unroll
    for (int ls = 4; ls >= 1; ls >>= 1) {
        int f = 64 / ls;
#pragma unroll
        for (int g = 0; g < 4 / ls; g++)
#pragma unroll
            for (int i = 0; i < ls; i++) {
                int t0 = g * 2 * ls + i, t1 = t0 + ls;
                float2 u = X[t0], v = X[t1];
                X[t0] = cadd(u, v);
                if (ls == 1) X[t1] = csub(u, v);            // tw = 1
                else         X[t1] = cmul(csub(u, v), W128[i * f]);
            }
    }
}

// radix-5 DFT with output twiddles W125[r*e]
__device__ __forceinline__ void bfly5(float2* x, int e, const float2* W125) {
    float2 y0 = cadd(cadd(cadd(cadd(x[0], x[1]), x[2]), x[3]), x[4]);
    float2 y1 = x[0]; y1 = cfma(y1, x[1], W5_1); y1 = cfma(y1, x[2], W5_2); y1 = cfma(y1, x[3], W5_3); y1 = cfma(y1, x[4], W5_4);
    float2 y2 = x[0]; y2 = cfma(y2, x[1], W5_2); y2 = cfma(y2, x[2], W5_4); y2 = cfma(y2, x[3], W5_1); y2 = cfma(y2, x[4], W5_3);
    float2 y3 = x[0]; y3 = cfma(y3, x[1], W5_3); y3 = cfma(y3, x[2], W5_1); y3 = cfma(y3, x[3], W5_4); y3 = cfma(y3, x[4], W5_2);
    float2 y4 = x[0]; y4 = cfma(y4, x[1], W5_4); y4 = cfma(y4, x[2], W5_3); y4 = cfma(y4, x[3], W5_2); y4 = cfma(y4, x[4], W5_1);
    if (e) {
        y1 = cmul(y1, W125[e]);
        y2 = cmul(y2, W125[2 * e]);
        y3 = cmul(y3, W125[3 * e]);
        y4 = cmul(y4, W125[4 * e]);
    }
    x[0] = y0; x[1] = y1; x[2] = y2; x[3] = y3; x[4] = y4;
}

// ---------------------------------------------------------------------------
// Forward FFT2, natural input layout (physical == logical). No reorder:
// leaves physical slot p holding F[sigma(p)], sigma = (brev7, digrev125).
// ---------------------------------------------------------------------------
__device__ void fft2_nat(float2* Z, const float2* W128, const float2* W125,
                         int tid, int NT) {
    // a-axis group 1: stages 64,32,16,8
    for (int u = tid; u < 1000; u += NT) {
        int j = u / 125, col = u - j * 125;
        float2 X[16];
#pragma unroll
        for (int t = 0; t < 16; t++) X[t] = Z[(j + 8 * t) * 125 + col];
        bfly16(X, j, W128);
#pragma unroll
        for (int t = 0; t < 16; t++) Z[(j + 8 * t) * 125 + col] = X[t];
    }
    __syncthreads();
    // a-axis group 2: stages 4,2,1
    for (int u = tid; u < 2000; u += NT) {
        int g = u / 125, col = u - g * 125;
        float2 X[8];
#pragma unroll
        for (int t = 0; t < 8; t++) X[t] = Z[(8 * g + t) * 125 + col];
        bfly8(X, W128);
#pragma unroll
        for (int t = 0; t < 8; t++) Z[(8 * g + t) * 125 + col] = X[t];
    }
    __syncthreads();
    // b-axis stage m=25: elems base + 25r, base = a*125 + c, tw e = c
    for (int u = tid; u < 3200; u += NT) {
        int a = u / 25, c = u - a * 25;
        int base = a * 125 + c;
        float2 x[5];
#pragma unroll
        for (int r = 0; r < 5; r++) x[r] = Z[base + 25 * r];
        bfly5(x, c, W125);
#pragma unroll
        for (int r = 0; r < 5; r++) Z[base + 25 * r] = x[r];
    }
    __syncthreads();
    // b-axis stage m=5: base = a*125 + blk*25 + j, elems + 5r, e = 5j
    for (int u = tid; u < 3200; u += NT) {
        int a = u / 25, rest = u - a * 25;
        int j = rest % 5, blk = rest / 5;
        int base = a * 125 + blk * 25 + j;
        float2 x[5];
#pragma unroll
        for (int r = 0; r < 5; r++) x[r] = Z[base + 5 * r];
        bfly5(x, 5 * j, W125);
#pragma unroll
        for (int r = 0; r < 5; r++) Z[base + 5 * r] = x[r];
    }
    __syncthreads();
    // b-axis stage m=1: base = a*125 + t*5, elems + r, no tw
    for (int u = tid; u < 3200; u += NT) {
        int a = u / 25, t = u - a * 25;
        int base = a * 125 + t * 5;
        float2 x[5];
#pragma unroll
        for (int r = 0; r < 5; r++) x[r] = Z[base + r];
        bfly5(x, 0, W125);
#pragma unroll
        for (int r = 0; r < 5; r++) Z[base + r] = x[r];
    }
    __syncthreads();
}

// ---------------------------------------------------------------------------
// Forward FFT2 executed with every access remapped through sigma
// (input stored at physical sigma(logical)). Output lands in NATURAL order.
// ---------------------------------------------------------------------------
__device__ void fft2_perm(float2* Z, const float2* W128, const float2* W125,
                          int tid, int NT) {
    // a-axis group 1: logical rows j+8t live at physical brev3(j)*16 + brev4(t)
    for (int u = tid; u < 1000; u += NT) {
        int j = u / 125, col = u - j * 125;
        int R0 = c_brev3[j] * 16;
        float2 X[16];
#pragma unroll
        for (int t = 0; t < 16; t++) X[t] = Z[(R0 + c_brev4[t]) * 125 + col];
        bfly16(X, j, W128);
#pragma unroll
        for (int t = 0; t < 16; t++) Z[(R0 + c_brev4[t]) * 125 + col] = X[t];
    }
    __syncthreads();
    // a-axis group 2: logical rows 8g+t live at physical brev3(t)*16 + brev4(g)
    for (int u = tid; u < 2000; u += NT) {
        int g = u / 125, col = u - g * 125;
        int G = c_brev4[g];
        float2 X[8];
#pragma unroll
        for (int t = 0; t < 8; t++) X[t] = Z[(c_brev3[t] * 16 + G) * 125 + col];
        bfly8(X, W128);
#pragma unroll
        for (int t = 0; t < 8; t++) Z[(c_brev3[t] * 16 + G) * 125 + col] = X[t];
    }
    __syncthreads();
    // b-axis m=25: logical b = c + 25t -> physical (c%5)*25 + (c/5)*5 + t
    for (int u = tid; u < 3200; u += NT) {
        int a = u / 25, c = u - a * 25;
        int base = a * 125 + (c % 5) * 25 + (c / 5) * 5;
        float2 x[5];
#pragma unroll
        for (int r = 0; r < 5; r++) x[r] = Z[base + r];
        bfly5(x, c, W125);
#pragma unroll
        for (int r = 0; r < 5; r++) Z[base + r] = x[r];
    }
    __syncthreads();
    // b-axis m=5: logical b = j + 5s + 25t -> physical j*25 + s*5 + t
    for (int u = tid; u < 3200; u += NT) {
        int a = u / 25, rest = u - a * 25;
        int j = rest / 5, t = rest % 5;
        int base = a * 125 + j * 25 + t;
        float2 x[5];
#pragma unroll
        for (int r = 0; r < 5; r++) x[r] = Z[base + 5 * r];
        bfly5(x, 5 * j, W125);
#pragma unroll
        for (int r = 0; r < 5; r++) Z[base + 5 * r] = x[r];
    }
    __syncthreads();
    // b-axis m=1: logical b = r + 5u2 -> physical r*25 + (u2%5)*5 + u2/5
    for (int u = tid; u < 3200; u += NT) {
        int a = u / 25, u2 = u - a * 25;
        int base = a * 125 + (u2 % 5) * 5 + u2 / 5;
        float2 x[5];
#pragma unroll
        for (int r = 0; r < 5; r++) x[r] = Z[base + 25 * r];
        bfly5(x, 0, W125);
#pragma unroll
        for (int r = 0; r < 5; r++) Z[base + 25 * r] = x[r];
    }
    __syncthreads();
}

// ---------------------------------------------------------------------------
// Kernel F: one CTA per batch row.
// ---------------------------------------------------------------------------
__global__ void __launch_bounds__(512)
mcb_fft_kernel(const float* __restrict__ x1,
               const float* __restrict__ x2,
               float* __restrict__ out) {
    extern __shared__ float2 sm[];
    float2* Z    = sm;             // 16000
    float2* W128 = sm + 16000;     // 128
    float2* W125 = sm + 16128;     // 125

    const int tid = threadIdx.x;
    const int NT  = blockDim.x;
    const int row = blockIdx.x;

    // init: zero grid (float4), fill twiddle tables
    float4* Z4 = (float4*)Z;
    for (int i = tid; i < 8000; i += NT) Z4[i] = make_float4(0.f, 0.f, 0.f, 0.f);
    if (tid < 128) {
        float s, c;
        sincosf(-6.283185307179586f * (float)tid / 128.f, &s, &c);
        W128[tid] = make_float2(c, s);
    }
    {
        int k = tid - 128;
        if (k >= 0 && k < 125) {
            float s, c;
            sincosf(-6.283185307179586f * (float)k / 125.f, &s, &c);
            W125[k] = make_float2(c, s);
        }
    }
    __syncthreads();

    // count-sketch scatter onto CRT-mapped 2-D grid (natural layout)
    const float* x1r = x1 + row * DD;
    const float* x2r = x2 + row * DD;
    for (int d = tid; d < DD; d += NT) {
        int n1 = g_idx1[d];
        float v1 = g_sgn1[d] * x1r[d];
        atomicAdd(&Z[(n1 & 127) * 125 + (n1 % 125)].x, v1);
        int n2 = g_idx2[d];
        float v2 = g_sgn2[d] * x2r[d];
        atomicAdd(&Z[(n2 & 127) * 125 + (n2 % 125)].y, v2);
    }
    __syncthreads();

    // forward FFT2 of z = y1 + i*y2; physical slot p holds Fz[sigma(p)]
    fft2_nat(Z, W128, W125, tid, NT);

    // Hermitian unpack + pointwise product in the PERMUTED domain.
    // Store conj(G[k]) at logical slot k == physical sigma(k).
    for (int p = tid; p < 16000; p += NT) {
        int pa = p / 125, pb = p - pa * 125;
        int ka = __brev((unsigned)pa) >> 25;
        int kb = digrev125(pb);
        int kam = (128 - ka) & 127;
        int kbm = (125 - kb) % 125;
        int pm = ((int)(__brev((unsigned)kam) >> 25)) * 125 + digrev125(kbm);
        if (pm < p) continue;               // one thread per {p, pm} pair
        float2 zk = Z[p], zm = Z[pm];
        float2 f1 = make_float2(0.5f * (zk.x + zm.x),  0.5f * (zk.y - zm.y));
        float2 f2 = make_float2(0.5f * (zk.y + zm.y), -0.5f * (zk.x - zm.x));
        float2 g  = cmul(f1, f2);
        Z[p]  = make_float2(g.x, -g.y);     // conj(G[k])
        Z[pm] = g;                          // conj(G[-k]) = G[k]
    }
    __syncthreads();

    // inverse via forward-on-conj in permuted layout; result lands natural.
    fft2_perm(Z, W128, W125, tid, NT);

    // emit real part, CRT map back to 1-D index
    const float scale = 1.0f / 16000.0f;
    float* outr = out + row * PP;
    for (int n = tid; n < PP; n += NT) {
        outr[n] = Z[(n & 127) * 125 + (n % 125)].x * scale;
    }
}

// ---------------------------------------------------------------------------
// Launch
// ---------------------------------------------------------------------------
extern "C" void kernel_launch(void* const* d_in, const int* in_sizes, int n_in,
                              void* d_out, int out_size) {
    const float* x1 = (const float*)d_in[0];
    const float* x2 = (const float*)d_in[1];
    const int4*  C1 = (const int4*)d_in[2];
    const int4*  C2 = (const int4*)d_in[3];
    float* out = (float*)d_out;

    const int B = in_sizes[0] / DD;           // 128

    extract_kernel<<<16000, 256>>>(C1, C2);

    const size_t smem = (size_t)(16000 + 128 + 125) * sizeof(float2); // 130,024 B
    cudaFuncSetAttribute(mcb_fft_kernel,
                         cudaFuncAttributeMaxDynamicSharedMemorySize, (int)smem);
    mcb_fft_kernel<<<B, 512, smem>>>(x1, x2, out);
}

// round 3
// speedup vs baseline: 1.5838x; 1.1345x over previous
#include <cuda_runtime.h>

#define DD 2048
#define PP 16000

// Sketch structure extracted from C1/C2 each launch (deterministic).
__device__ int   g_idx1[DD], g_idx2[DD];
__device__ float g_sgn1[DD], g_sgn2[DD];

// ---------------------------------------------------------------------------
// Kernel E: parse BOTH dense count-sketch matrices [D, P] -> (idx, sign).
// Pure streaming read (262 MB); hits are rare. 8 independent loads/thread.
// ---------------------------------------------------------------------------
__global__ void extract_kernel(const int4* __restrict__ C1,
                               const int4* __restrict__ C2) {
    int b = blockIdx.x;                      // 8000 blocks total
    const int4* C;
    int*  idx;
    float* sgn;
    int mb;
    if (b < 4000) { C = C1; idx = g_idx1; sgn = g_sgn1; mb = b; }
    else          { C = C2; idx = g_idx2; sgn = g_sgn2; mb = b - 4000; }
    int base = mb * 2048 + threadIdx.x;      // 2048 int4 per block
#pragma unroll
    for (int k = 0; k < 8; k++) {
        int i4 = base + k * 256;
        int4 v = __ldcs(&C[i4]);
        if (v.x | v.y | v.z | v.w) {
            int e = i4 * 4;
            if (v.x) { idx[e / PP] = e % PP; sgn[e / PP] = __int_as_float(v.x); }
            if (v.y) { int q = e + 1; idx[q / PP] = q % PP; sgn[q / PP] = __int_as_float(v.y); }
            if (v.z) { int q = e + 2; idx[q / PP] = q % PP; sgn[q / PP] = __int_as_float(v.z); }
            if (v.w) { int q = e + 3; idx[q / PP] = q % PP; sgn[q / PP] = __int_as_float(v.w); }
        }
    }
}

// ---------------------------------------------------------------------------
// Complex helpers
// ---------------------------------------------------------------------------
__device__ __forceinline__ float2 cadd(float2 a, float2 b) { return make_float2(a.x + b.x, a.y + b.y); }
__device__ __forceinline__ float2 csub(float2 a, float2 b) { return make_float2(a.x - b.x, a.y - b.y); }
__device__ __forceinline__ float2 cmul(float2 a, float2 b) {
    return make_float2(a.x * b.x - a.y * b.y, a.x * b.y + a.y * b.x);
}
__device__ __forceinline__ float2 cfma(float2 acc, float2 a, float2 b) {
    acc.x = fmaf(a.x, b.x, fmaf(-a.y, b.y, acc.x));
    acc.y = fmaf(a.x, b.y, fmaf(a.y, b.x, acc.y));
    return acc;
}

// 5th roots of unity: W5^k = exp(-2*pi*i*k/5)
#define W5_1 make_float2( 0.30901699437494745f, -0.9510565162951535f)
#define W5_2 make_float2(-0.8090169943749473f,  -0.5877852522924731f)
#define W5_3 make_float2(-0.8090169943749475f,   0.5877852522924730f)
#define W5_4 make_float2( 0.30901699437494723f,  0.9510565162951536f)

__device__ __constant__ int c_brev4[16] = {0,8,4,12,2,10,6,14,1,9,5,13,3,11,7,15};
__device__ __constant__ int c_brev3[8]  = {0,4,2,6,1,5,3,7};

// cheap small divisions (valid for the ranges used)
__device__ __forceinline__ int div5(int x)  { return (x * 205) >> 10; }   // x < 600
__device__ __forceinline__ int div25(int x) { return (x * 41)  >> 10; }   // x < 600
__device__ __forceinline__ int mod125_16k(int x, int& q) {                // x <= 16000
    q = (int)(((unsigned)x * 8389u) >> 20);
    return x - q * 125;
}
__device__ __forceinline__ int digrev125(int b) {
    int d12 = div5(b);          // b / 5
    int d2  = div25(b);         // b / 25
    int d0  = b - d12 * 5;
    int d1  = d12 - d2 * 5;
    return d0 * 25 + d1 * 5 + d2;
}
__device__ __forceinline__ int brev7(int a) { return (int)(__brev((unsigned)a) >> 25); }

// ---------------------------------------------------------------------------
// Fused radix-2 butterfly blocks (DIF, logical t-order).
// bfly16: stages m = 64,32,16,8.  a = j + 8*t.
// bfly8 : stages m =  4, 2, 1.    a = 8*g + t.
// ---------------------------------------------------------------------------
__device__ __forceinline__ void bfly16(float2* X, int j, const float2* W128) {
#pragma unroll
    for (int ls = 8; ls >= 1; ls >>= 1) {
        int f = 8 / ls;
#pragma unroll
        for (int g = 0; g < 8 / ls; g++)
#pragma unroll
            for (int i = 0; i < ls; i++) {
                int t0 = g * 2 * ls + i, t1 = t0 + ls;
                float2 u = X[t0], v = X[t1];
                X[t0] = cadd(u, v);
                X[t1] = cmul(csub(u, v), W128[(j + 8 * i) * f]);
            }
    }
}

__device__ __forceinline__ void bfly8(float2* X, const float2* W128) {
#pragma unroll
    for (int ls = 4; ls >= 1; ls >>= 1) {
        int f = 64 / ls;
#pragma unroll
        for (int g = 0; g < 4 / ls; g++)
#pragma unroll
            for (int i = 0; i < ls; i++) {
                int t0 = g * 2 * ls + i, t1 = t0 + ls;
                float2 u = X[t0], v = X[t1];
                X[t0] = cadd(u, v);
                if (ls == 1) X[t1] = csub(u, v);
                else         X[t1] = cmul(csub(u, v), W128[i * f]);
            }
    }
}

// radix-5 DFT with output twiddles W125[r*e]
__device__ __forceinline__ void bfly5(float2* x, int e, const float2* W125) {
    float2 y0 = cadd(cadd(cadd(cadd(x[0], x[1]), x[2]), x[3]), x[4]);
    float2 y1 = x[0]; y1 = cfma(y1, x[1], W5_1); y1 = cfma(y1, x[2], W5_2); y1 = cfma(y1, x[3], W5_3); y1 = cfma(y1, x[4], W5_4);
    float2 y2 = x[0]; y2 = cfma(y2, x[1], W5_2); y2 = cfma(y2, x[2], W5_4); y2 = cfma(y2, x[3], W5_1); y2 = cfma(y2, x[4], W5_3);
    float2 y3 = x[0]; y3 = cfma(y3, x[1], W5_3); y3 = cfma(y3, x[2], W5_1); y3 = cfma(y3, x[3], W5_4); y3 = cfma(y3, x[4], W5_2);
    float2 y4 = x[0]; y4 = cfma(y4, x[1], W5_4); y4 = cfma(y4, x[2], W5_3); y4 = cfma(y4, x[3], W5_2); y4 = cfma(y4, x[4], W5_1);
    if (e) {
        y1 = cmul(y1, W125[e]);
        y2 = cmul(y2, W125[2 * e]);
        y3 = cmul(y3, W125[3 * e]);
        y4 = cmul(y4, W125[4 * e]);
    }
    x[0] = y0; x[1] = y1; x[2] = y2; x[3] = y3; x[4] = y4;
}

#define NTHR 1024

// ---------------------------------------------------------------------------
// Forward FFT2, natural layout in -> sigma-permuted out.
// All thread mappings are shift/mask (some lanes idle), no divisions.
// ---------------------------------------------------------------------------
__device__ void fft2_nat(float2* Z, const float2* W128, const float2* W125,
                         int tid) {
    // a-axis group 1: 8 j x 125 col  (1024 slots, 1 iter)
    {
        int j = tid >> 7, col = tid & 127;
        if (col < 125) {
            float2 X[16];
#pragma unroll
            for (int t = 0; t < 16; t++) X[t] = Z[(j + 8 * t) * 125 + col];
            bfly16(X, j, W128);
#pragma unroll
            for (int t = 0; t < 16; t++) Z[(j + 8 * t) * 125 + col] = X[t];
        }
    }
    __syncthreads();
    // a-axis group 2: 16 g x 125 col  (2048 slots, 2 iters)
#pragma unroll
    for (int it = 0; it < 2; it++) {
        int idx = tid + it * NTHR;
        int g = idx >> 7, col = idx & 127;
        if (col < 125) {
            float2 X[8];
#pragma unroll
            for (int t = 0; t < 8; t++) X[t] = Z[(8 * g + t) * 125 + col];
            bfly8(X, W128);
#pragma unroll
            for (int t = 0; t < 8; t++) Z[(8 * g + t) * 125 + col] = X[t];
        }
    }
    __syncthreads();
    // b-axis m=25: 128 a x 25 c  (4096 slots, 4 iters)
#pragma unroll
    for (int it = 0; it < 4; it++) {
        int idx = tid + it * NTHR;
        int a = idx >> 5, c = idx & 31;
        if (c < 25) {
            int base = a * 125 + c;
            float2 x[5];
#pragma unroll
            for (int r = 0; r < 5; r++) x[r] = Z[base + 25 * r];
            bfly5(x, c, W125);
#pragma unroll
            for (int r = 0; r < 5; r++) Z[base + 25 * r] = x[r];
        }
    }
    __syncthreads();
    // b-axis m=5: c -> (blk = c/5, j = c%5), base = a*125 + blk*25 + j, +5r
#pragma unroll
    for (int it = 0; it < 4; it++) {
        int idx = tid + it * NTHR;
        int a = idx >> 5, c = idx & 31;
        if (c < 25) {
            int blk = div5(c), j = c - blk * 5;
            int base = a * 125 + blk * 25 + j;
            float2 x[5];
#pragma unroll
            for (int r = 0; r < 5; r++) x[r] = Z[base + 5 * r];
            bfly5(x, 5 * j, W125);
#pragma unroll
            for (int r = 0; r < 5; r++) Z[base + 5 * r] = x[r];
        }
    }
    __syncthreads();
    // b-axis m=1: base = a*125 + c*5, +r, no tw
#pragma unroll
    for (int it = 0; it < 4; it++) {
        int idx = tid + it * NTHR;
        int a = idx >> 5, c = idx & 31;
        if (c < 25) {
            int base = a * 125 + c * 5;
            float2 x[5];
#pragma unroll
            for (int r = 0; r < 5; r++) x[r] = Z[base + r];
            bfly5(x, 0, W125);
#pragma unroll
            for (int r = 0; r < 5; r++) Z[base + r] = x[r];
        }
    }
    __syncthreads();
}

// ---------------------------------------------------------------------------
// Forward FFT2 with all accesses remapped through sigma; output lands natural.
// ---------------------------------------------------------------------------
__device__ void fft2_perm(float2* Z, const float2* W128, const float2* W125,
                          int tid) {
    // a-axis group 1: logical rows j+8t at physical brev3(j)*16 + brev4(t)
    {
        int j = tid >> 7, col = tid & 127;
        if (col < 125) {
            int R0 = c_brev3[j] * 16;
            float2 X[16];
#pragma unroll
            for (int t = 0; t < 16; t++) X[t] = Z[(R0 + c_brev4[t]) * 125 + col];
            bfly16(X, j, W128);
#pragma unroll
            for (int t = 0; t < 16; t++) Z[(R0 + c_brev4[t]) * 125 + col] = X[t];
        }
    }
    __syncthreads();
    // a-axis group 2: logical rows 8g+t at physical brev3(t)*16 + brev4(g)
#pragma unroll
    for (int it = 0; it < 2; it++) {
        int idx = tid + it * NTHR;
        int g = idx >> 7, col = idx & 127;
        if (col < 125) {
            int G = c_brev4[g];
            float2 X[8];
#pragma unroll
            for (int t = 0; t < 8; t++) X[t] = Z[(c_brev3[t] * 16 + G) * 125 + col];
            bfly8(X, W128);
#pragma unroll
            for (int t = 0; t < 8; t++) Z[(c_brev3[t] * 16 + G) * 125 + col] = X[t];
        }
    }
    __syncthreads();
    // b-axis m=25: logical b = c + 25t -> physical (c%5)*25 + (c/5)*5 + t
#pragma unroll
    for (int it = 0; it < 4; it++) {
        int idx = tid + it * NTHR;
        int a = idx >> 5, c = idx & 31;
        if (c < 25) {
            int ch = div5(c), cl = c - ch * 5;
            int base = a * 125 + cl * 25 + ch * 5;
            float2 x[5];
#pragma unroll
            for (int r = 0; r < 5; r++) x[r] = Z[base + r];
            bfly5(x, c, W125);
#pragma unroll
            for (int r = 0; r < 5; r++) Z[base + r] = x[r];
        }
    }
    __syncthreads();
    // b-axis m=5: logical b = j + 5s + 25t -> physical j*25 + s*5 + t
#pragma unroll
    for (int it = 0; it < 4; it++) {
        int idx = tid + it * NTHR;
        int a = idx >> 5, c = idx & 31;
        if (c < 25) {
            int j = div5(c), t = c - j * 5;
            int base = a * 125 + j * 25 + t;
            float2 x[5];
#pragma unroll
            for (int r = 0; r < 5; r++) x[r] = Z[base + 5 * r];
            bfly5(x, 5 * j, W125);
#pragma unroll
            for (int r = 0; r < 5; r++) Z[base + 5 * r] = x[r];
        }
    }
    __syncthreads();
    // b-axis m=1: logical b = r + 5u2 -> physical r*25 + (u2%5)*5 + u2/5
#pragma unroll
    for (int it = 0; it < 4; it++) {
        int idx = tid + it * NTHR;
        int a = idx >> 5, c = idx & 31;
        if (c < 25) {
            int ch = div5(c), cl = c - ch * 5;
            int base = a * 125 + cl * 5 + ch;
            float2 x[5];
#pragma unroll
            for (int r = 0; r < 5; r++) x[r] = Z[base + 25 * r];
            bfly5(x, 0, W125);
#pragma unroll
            for (int r = 0; r < 5; r++) Z[base + 25 * r] = x[r];
        }
    }
    __syncthreads();
}

// ---------------------------------------------------------------------------
// Kernel F: one CTA per batch row.
// ---------------------------------------------------------------------------
__global__ void __launch_bounds__(NTHR, 1)
mcb_fft_kernel(const float* __restrict__ x1,
               const float* __restrict__ x2,
               float* __restrict__ out) {
    extern __shared__ float2 sm[];
    float2* Z    = sm;             // 16000
    float2* W128 = sm + 16000;     // 128
    float2* W125 = sm + 16128;     // 125

    const int tid = threadIdx.x;
    const int row = blockIdx.x;

    // init: zero grid (float4), fill twiddle tables
    float4* Z4 = (float4*)Z;
#pragma unroll
    for (int it = 0; it < 8; it++) {
        int i = tid + it * NTHR;
        if (i < 8000) Z4[i] = make_float4(0.f, 0.f, 0.f, 0.f);
    }
    if (tid < 128) {
        float s, c;
        sincosf(-6.283185307179586f * (float)tid / 128.f, &s, &c);
        W128[tid] = make_float2(c, s);
    }
    {
        int k = tid - 128;
        if (k >= 0 && k < 125) {
            float s, c;
            sincosf(-6.283185307179586f * (float)k / 125.f, &s, &c);
            W125[k] = make_float2(c, s);
        }
    }
    __syncthreads();

    // count-sketch scatter onto CRT-mapped 2-D grid (natural layout)
    const float* x1r = x1 + row * DD;
    const float* x2r = x2 + row * DD;
#pragma unroll
    for (int it = 0; it < 2; it++) {
        int d = tid + it * NTHR;
        int q1, q2;
        int n1 = g_idx1[d];
        float v1 = g_sgn1[d] * x1r[d];
        int b1 = mod125_16k(n1, q1);
        atomicAdd(&Z[(n1 & 127) * 125 + b1].x, v1);
        int n2 = g_idx2[d];
        float v2 = g_sgn2[d] * x2r[d];
        int b2 = mod125_16k(n2, q2);
        atomicAdd(&Z[(n2 & 127) * 125 + b2].y, v2);
    }
    __syncthreads();

    // forward FFT2 of z = y1 + i*y2; physical slot p holds Fz[sigma(p)]
    fft2_nat(Z, W128, W125, tid);

    // Hermitian unpack + pointwise product, enumerating LOGICAL k in [0, 8000].
    // F[k] sits at physical p = sigma(k); partner F[-k] at pm = sigma(-k).
    for (int k = tid; k <= 8000; k += NTHR) {
        int ka = k & 127;
        int q;
        int kb = mod125_16k(k, q);
        int p  = brev7(ka) * 125 + digrev125(kb);
        int kam = (128 - ka) & 127;
        int kbm = (kb == 0) ? 0 : 125 - kb;
        int pm  = brev7(kam) * 125 + digrev125(kbm);
        float2 zk = Z[p], zm = Z[pm];
        float2 f1 = make_float2(0.5f * (zk.x + zm.x),  0.5f * (zk.y - zm.y));
        float2 f2 = make_float2(0.5f * (zk.y + zm.y), -0.5f * (zk.x - zm.x));
        float2 g  = cmul(f1, f2);
        Z[p]  = make_float2(g.x, -g.y);     // conj(G[k])
        Z[pm] = g;                          // conj(G[-k]) = G[k]
    }
    __syncthreads();

    // inverse via forward-on-conj in permuted layout; result lands natural.
    fft2_perm(Z, W128, W125, tid);

    // emit real part, CRT map back to 1-D index
    const float scale = 1.0f / 16000.0f;
    float* outr = out + row * PP;
#pragma unroll
    for (int it = 0; it < 16; it++) {
        int n = tid + it * NTHR;
        if (n < PP) {
            int q;
            int b = mod125_16k(n, q);
            outr[n] = Z[(n & 127) * 125 + b].x * scale;
        }
    }
}

// ---------------------------------------------------------------------------
// Launch
// ---------------------------------------------------------------------------
extern "C" void kernel_launch(void* const* d_in, const int* in_sizes, int n_in,
                              void* d_out, int out_size) {
    const float* x1 = (const float*)d_in[0];
    const float* x2 = (const float*)d_in[1];
    const int4*  C1 = (const int4*)d_in[2];
    const int4*  C2 = (const int4*)d_in[3];
    float* out = (float*)d_out;

    const int B = in_sizes[0] / DD;           // 128

    extract_kernel<<<8000, 256>>>(C1, C2);

    const size_t smem = (size_t)(16000 + 128 + 125) * sizeof(float2); // 130,024 B
    cudaFuncSetAttribute(mcb_fft_kernel,
                         cudaFuncAttributeMaxDynamicSharedMemorySize, (int)smem);
    mcb_fft_kernel<<<B, NTHR, smem>>>(x1, x2, out);
}

// round 4
// speedup vs baseline: 1.9441x; 1.2275x over previous
#include <cuda_runtime.h>

#define DD 2048
#define PP 16000

// Sketch structure extracted from C1/C2 each launch (deterministic).
__device__ int   g_idx1[DD], g_idx2[DD];
__device__ float g_sgn1[DD], g_sgn2[DD];

// ---------------------------------------------------------------------------
// Kernel E: one CTA per C-row; early-exit scan for the single nonzero.
// Expected DRAM traffic ~0.56 * 262 MB.
// ---------------------------------------------------------------------------
__global__ void __launch_bounds__(256)
extract_kernel(const float4* __restrict__ C1, const float4* __restrict__ C2) {
    int d = blockIdx.x;                       // 0..4095
    const float4* rowp;
    int*  idx;
    float* sgn;
    int r;
    if (d < DD) { rowp = C1 + (size_t)d * 4000;        idx = g_idx1; sgn = g_sgn1; r = d; }
    else        { rowp = C2 + (size_t)(d - DD) * 4000; idx = g_idx2; sgn = g_sgn2; r = d - DD; }

    __shared__ int found;
    if (threadIdx.x == 0) found = 0;
    __syncthreads();

    // 4000 float4 per row; chunks of 512 float4 (2 per thread), 8 chunks max.
#pragma unroll 1
    for (int c = 0; c < 8; c++) {
        int base = c * 512 + threadIdx.x;
#pragma unroll
        for (int k = 0; k < 2; k++) {
            int i = base + k * 256;
            if (i < 4000) {
                float4 v = __ldcs(&rowp[i]);
                if (v.x != 0.f || v.y != 0.f || v.z != 0.f || v.w != 0.f) {
                    int e = i * 4;
                    if      (v.x != 0.f) { idx[r] = e;     sgn[r] = v.x; }
                    else if (v.y != 0.f) { idx[r] = e + 1; sgn[r] = v.y; }
                    else if (v.z != 0.f) { idx[r] = e + 2; sgn[r] = v.z; }
                    else                 { idx[r] = e + 3; sgn[r] = v.w; }
                    found = 1;
                }
            }
        }
        __syncthreads();
        if (found) break;
    }
}

// ---------------------------------------------------------------------------
// Complex helpers
// ---------------------------------------------------------------------------
__device__ __forceinline__ float2 cadd(float2 a, float2 b) { return make_float2(a.x + b.x, a.y + b.y); }
__device__ __forceinline__ float2 csub(float2 a, float2 b) { return make_float2(a.x - b.x, a.y - b.y); }
__device__ __forceinline__ float2 cmul(float2 a, float2 b) {
    return make_float2(a.x * b.x - a.y * b.y, a.x * b.y + a.y * b.x);
}
__device__ __forceinline__ float2 cfma(float2 acc, float2 a, float2 b) {
    acc.x = fmaf(a.x, b.x, fmaf(-a.y, b.y, acc.x));
    acc.y = fmaf(a.x, b.y, fmaf(a.y, b.x, acc.y));
    return acc;
}

// 5th roots of unity: W5^k = exp(-2*pi*i*k/5)
#define W5_1 make_float2( 0.30901699437494745f, -0.9510565162951535f)
#define W5_2 make_float2(-0.8090169943749473f,  -0.5877852522924731f)
#define W5_3 make_float2(-0.8090169943749475f,   0.5877852522924730f)
#define W5_4 make_float2( 0.30901699437494723f,  0.9510565162951536f)

__device__ __constant__ int c_brev4[16] = {0,8,4,12,2,10,6,14,1,9,5,13,3,11,7,15};
__device__ __constant__ int c_brev3[8]  = {0,4,2,6,1,5,3,7};

// cheap small divisions (valid for the ranges used)
__device__ __forceinline__ int div5(int x)  { return (x * 205) >> 10; }   // x < 1024
__device__ __forceinline__ int div25(int x) { return (x * 41)  >> 10; }   // x < 600
__device__ __forceinline__ int mod125_16k(int x, int& q) {                // x <= 16000
    q = (int)(((unsigned)x * 8389u) >> 20);
    return x - q * 125;
}
__device__ __forceinline__ int digrev125(int b) {
    int d12 = div5(b);          // b / 5
    int d2  = div25(b);         // b / 25
    int d0  = b - d12 * 5;
    int d1  = d12 - d2 * 5;
    return d0 * 25 + d1 * 5 + d2;
}
__device__ __forceinline__ int brev7(int a) { return (int)(__brev((unsigned)a) >> 25); }

// ---------------------------------------------------------------------------
// Fused radix-2 butterfly blocks (DIF, logical t-order).
// ---------------------------------------------------------------------------
__device__ __forceinline__ void bfly16(float2* X, int j, const float2* W128) {
#pragma unroll
    for (int ls = 8; ls >= 1; ls >>= 1) {
        int f = 8 / ls;
#pragma unroll
        for (int g = 0; g < 8 / ls; g++)
#pragma unroll
            for (int i = 0; i < ls; i++) {
                int t0 = g * 2 * ls + i, t1 = t0 + ls;
                float2 u = X[t0], v = X[t1];
                X[t0] = cadd(u, v);
                X[t1] = cmul(csub(u, v), W128[(j + 8 * i) * f]);
            }
    }
}

__device__ __forceinline__ void bfly8(float2* X, const float2* W128) {
#pragma unroll
    for (int ls = 4; ls >= 1; ls >>= 1) {
        int f = 64 / ls;
#pragma unroll
        for (int g = 0; g < 4 / ls; g++)
#pragma unroll
            for (int i = 0; i < ls; i++) {
                int t0 = g * 2 * ls + i, t1 = t0 + ls;
                float2 u = X[t0], v = X[t1];
                X[t0] = cadd(u, v);
                if (ls == 1) X[t1] = csub(u, v);
                else         X[t1] = cmul(csub(u, v), W128[i * f]);
            }
    }
}

// radix-5 DFT with output twiddles W125[r*e]
__device__ __forceinline__ void bfly5(float2* x, int e, const float2* W125) {
    float2 y0 = cadd(cadd(cadd(cadd(x[0], x[1]), x[2]), x[3]), x[4]);
    float2 y1 = x[0]; y1 = cfma(y1, x[1], W5_1); y1 = cfma(y1, x[2], W5_2); y1 = cfma(y1, x[3], W5_3); y1 = cfma(y1, x[4], W5_4);
    float2 y2 = x[0]; y2 = cfma(y2, x[1], W5_2); y2 = cfma(y2, x[2], W5_4); y2 = cfma(y2, x[3], W5_1); y2 = cfma(y2, x[4], W5_3);
    float2 y3 = x[0]; y3 = cfma(y3, x[1], W5_3); y3 = cfma(y3, x[2], W5_1); y3 = cfma(y3, x[3], W5_4); y3 = cfma(y3, x[4], W5_2);
    float2 y4 = x[0]; y4 = cfma(y4, x[1], W5_4); y4 = cfma(y4, x[2], W5_3); y4 = cfma(y4, x[3], W5_2); y4 = cfma(y4, x[4], W5_1);
    if (e) {
        y1 = cmul(y1, W125[e]);
        y2 = cmul(y2, W125[2 * e]);
        y3 = cmul(y3, W125[3 * e]);
        y4 = cmul(y4, W125[4 * e]);
    }
    x[0] = y0; x[1] = y1; x[2] = y2; x[3] = y3; x[4] = y4;
}

// fused stages m=5 (tw 5j) and m=1 over 25 register-resident values.
// m=5 couples y[j + 5r]; m=1 couples y[5g + r].
__device__ __forceinline__ void bfly25_m5_m1(float2* y, const float2* W125) {
#pragma unroll
    for (int j = 0; j < 5; j++) {
        float2 x[5];
#pragma unroll
        for (int r = 0; r < 5; r++) x[r] = y[j + 5 * r];
        bfly5(x, 5 * j, W125);
#pragma unroll
        for (int r = 0; r < 5; r++) y[j + 5 * r] = x[r];
    }
#pragma unroll
    for (int g = 0; g < 5; g++) {
        bfly5(&y[5 * g], 0, W125);
    }
}

// fused stages m=5 and m=1 in the sigma-permuted layout, local index i = 5j+s:
// m=5 couples y[5j + s] (contiguous), m=1 couples y[s + 5j] (stride 5).
__device__ __forceinline__ void bfly25_m5_m1_perm(float2* y, const float2* W125) {
#pragma unroll
    for (int j = 0; j < 5; j++) {
        bfly5(&y[5 * j], 5 * j, W125);
    }
#pragma unroll
    for (int s = 0; s < 5; s++) {
        float2 x[5];
#pragma unroll
        for (int j = 0; j < 5; j++) x[j] = y[s + 5 * j];
        bfly5(x, 0, W125);
#pragma unroll
        for (int j = 0; j < 5; j++) y[s + 5 * j] = x[j];
    }
}

#define NTHR 1024

// ---------------------------------------------------------------------------
// Forward FFT2, natural layout in -> sigma-permuted out. 4 passes.
// ---------------------------------------------------------------------------
__device__ void fft2_nat(float2* Z, const float2* W128, const float2* W125,
                         int tid) {
    // a-axis group 1: stages 64,32,16,8
    {
        int j = tid >> 7, col = tid & 127;
        if (col < 125) {
            float2 X[16];
#pragma unroll
            for (int t = 0; t < 16; t++) X[t] = Z[(j + 8 * t) * 125 + col];
            bfly16(X, j, W128);
#pragma unroll
            for (int t = 0; t < 16; t++) Z[(j + 8 * t) * 125 + col] = X[t];
        }
    }
    __syncthreads();
    // a-axis group 2: stages 4,2,1
#pragma unroll
    for (int it = 0; it < 2; it++) {
        int idx = tid + it * NTHR;
        int g = idx >> 7, col = idx & 127;
        if (col < 125) {
            float2 X[8];
#pragma unroll
            for (int t = 0; t < 8; t++) X[t] = Z[(8 * g + t) * 125 + col];
            bfly8(X, W128);
#pragma unroll
            for (int t = 0; t < 8; t++) Z[(8 * g + t) * 125 + col] = X[t];
        }
    }
    __syncthreads();
    // b-axis m=25: 128 a x 25 c
#pragma unroll
    for (int it = 0; it < 4; it++) {
        int idx = tid + it * NTHR;
        int a = idx >> 5, c = idx & 31;
        if (c < 25) {
            int base = a * 125 + c;
            float2 x[5];
#pragma unroll
            for (int r = 0; r < 5; r++) x[r] = Z[base + 25 * r];
            bfly5(x, c, W125);
#pragma unroll
            for (int r = 0; r < 5; r++) Z[base + 25 * r] = x[r];
        }
    }
    __syncthreads();
    // b-axis fused m=5 & m=1: 128 a x 5 t, contiguous 25-blocks
    {
        int u = tid;                       // 640 units
        if (u < 640) {
            int a = div5(u), t = u - 5 * a;
            int base = a * 125 + t * 25;
            float2 y[25];
#pragma unroll
            for (int i = 0; i < 25; i++) y[i] = Z[base + i];
            bfly25_m5_m1(y, W125);
#pragma unroll
            for (int i = 0; i < 25; i++) Z[base + i] = y[i];
        }
    }
    __syncthreads();
}

// ---------------------------------------------------------------------------
// Forward FFT2 with accesses remapped through sigma; output lands natural.
// ---------------------------------------------------------------------------
__device__ void fft2_perm(float2* Z, const float2* W128, const float2* W125,
                          int tid) {
    // a-axis group 1: logical rows j+8t at physical brev3(j)*16 + brev4(t)
    {
        int j = tid >> 7, col = tid & 127;
        if (col < 125) {
            int R0 = c_brev3[j] * 16;
            float2 X[16];
#pragma unroll
            for (int t = 0; t < 16; t++) X[t] = Z[(R0 + c_brev4[t]) * 125 + col];
            bfly16(X, j, W128);
#pragma unroll
            for (int t = 0; t < 16; t++) Z[(R0 + c_brev4[t]) * 125 + col] = X[t];
        }
    }
    __syncthreads();
    // a-axis group 2: logical rows 8g+t at physical brev3(t)*16 + brev4(g)
#pragma unroll
    for (int it = 0; it < 2; it++) {
        int idx = tid + it * NTHR;
        int g = idx >> 7, col = idx & 127;
        if (col < 125) {
            int G = c_brev4[g];
            float2 X[8];
#pragma unroll
            for (int t = 0; t < 8; t++) X[t] = Z[(c_brev3[t] * 16 + G) * 125 + col];
            bfly8(X, W128);
#pragma unroll
            for (int t = 0; t < 8; t++) Z[(c_brev3[t] * 16 + G) * 125 + col] = X[t];
        }
    }
    __syncthreads();
    // b-axis m=25: logical b = c + 25t -> physical (c%5)*25 + (c/5)*5 + t
#pragma unroll
    for (int it = 0; it < 4; it++) {
        int idx = tid + it * NTHR;
        int a = idx >> 5, c = idx & 31;
        if (c < 25) {
            int ch = div5(c), cl = c - ch * 5;
            int base = a * 125 + cl * 25 + ch * 5;
            float2 x[5];
#pragma unroll
            for (int r = 0; r < 5; r++) x[r] = Z[base + r];
            bfly5(x, c, W125);
#pragma unroll
            for (int r = 0; r < 5; r++) Z[base + r] = x[r];
        }
    }
    __syncthreads();
    // b-axis fused m=5 & m=1: fixed (a, t), elements Z[a*125 + t + 5i]
    {
        int u = tid;                       // 640 units
        if (u < 640) {
            int a = div5(u), t = u - 5 * a;
            int base = a * 125 + t;
            float2 y[25];
#pragma unroll
            for (int i = 0; i < 25; i++) y[i] = Z[base + 5 * i];
            bfly25_m5_m1_perm(y, W125);
#pragma unroll
            for (int i = 0; i < 25; i++) Z[base + 5 * i] = y[i];
        }
    }
    __syncthreads();
}

// ---------------------------------------------------------------------------
// Kernel F: one CTA per batch row.
// ---------------------------------------------------------------------------
__global__ void __launch_bounds__(NTHR, 1)
mcb_fft_kernel(const float* __restrict__ x1,
               const float* __restrict__ x2,
               float* __restrict__ out) {
    extern __shared__ float2 sm[];
    float2* Z    = sm;             // 16000
    float2* W128 = sm + 16000;     // 128
    float2* W125 = sm + 16128;     // 125

    const int tid = threadIdx.x;
    const int row = blockIdx.x;

    // init: zero grid (float4), fill twiddle tables
    float4* Z4 = (float4*)Z;
#pragma unroll
    for (int it = 0; it < 8; it++) {
        int i = tid + it * NTHR;
        if (i < 8000) Z4[i] = make_float4(0.f, 0.f, 0.f, 0.f);
    }
    if (tid < 128) {
        float s, c;
        sincosf(-6.283185307179586f * (float)tid / 128.f, &s, &c);
        W128[tid] = make_float2(c, s);
    }
    {
        int k = tid - 128;
        if (k >= 0 && k < 125) {
            float s, c;
            sincosf(-6.283185307179586f * (float)k / 125.f, &s, &c);
            W125[k] = make_float2(c, s);
        }
    }
    __syncthreads();

    // count-sketch scatter onto CRT-mapped 2-D grid (natural layout)
    const float* x1r = x1 + row * DD;
    const float* x2r = x2 + row * DD;
#pragma unroll
    for (int it = 0; it < 2; it++) {
        int d = tid + it * NTHR;
        int q1, q2;
        int n1 = g_idx1[d];
        float v1 = g_sgn1[d] * x1r[d];
        int b1 = mod125_16k(n1, q1);
        atomicAdd(&Z[(n1 & 127) * 125 + b1].x, v1);
        int n2 = g_idx2[d];
        float v2 = g_sgn2[d] * x2r[d];
        int b2 = mod125_16k(n2, q2);
        atomicAdd(&Z[(n2 & 127) * 125 + b2].y, v2);
    }
    __syncthreads();

    // forward FFT2 of z = y1 + i*y2; physical slot p holds Fz[sigma(p)]
    fft2_nat(Z, W128, W125, tid);

    // Hermitian unpack + pointwise product, enumerating LOGICAL k in [0, 8000].
    for (int k = tid; k <= 8000; k += NTHR) {
        int ka = k & 127;
        int q;
        int kb = mod125_16k(k, q);
        int p  = brev7(ka) * 125 + digrev125(kb);
        int kam = (128 - ka) & 127;
        int kbm = (kb == 0) ? 0 : 125 - kb;
        int pm  = brev7(kam) * 125 + digrev125(kbm);
        float2 zk = Z[p], zm = Z[pm];
        float2 f1 = make_float2(0.5f * (zk.x + zm.x),  0.5f * (zk.y - zm.y));
        float2 f2 = make_float2(0.5f * (zk.y + zm.y), -0.5f * (zk.x - zm.x));
        float2 g  = cmul(f1, f2);
        Z[p]  = make_float2(g.x, -g.y);     // conj(G[k])
        Z[pm] = g;                          // conj(G[-k]) = G[k]
    }
    __syncthreads();

    // inverse via forward-on-conj in permuted layout; result lands natural.
    fft2_perm(Z, W128, W125, tid);

    // emit real part, CRT map back to 1-D index
    const float scale = 1.0f / 16000.0f;
    float* outr = out + row * PP;
#pragma unroll
    for (int it = 0; it < 16; it++) {
        int n = tid + it * NTHR;
        if (n < PP) {
            int q;
            int b = mod125_16k(n, q);
            outr[n] = Z[(n & 127) * 125 + b].x * scale;
        }
    }
}

// ---------------------------------------------------------------------------
// Launch
// ---------------------------------------------------------------------------
extern "C" void kernel_launch(void* const* d_in, const int* in_sizes, int n_in,
                              void* d_out, int out_size) {
    const float*  x1 = (const float*)d_in[0];
    const float*  x2 = (const float*)d_in[1];
    const float4* C1 = (const float4*)d_in[2];
    const float4* C2 = (const float4*)d_in[3];
    float* out = (float*)d_out;

    const int B = in_sizes[0] / DD;           // 128

    extract_kernel<<<2 * DD, 256>>>(C1, C2);

    const size_t smem = (size_t)(16000 + 128 + 125) * sizeof(float2); // 130,024 B
    cudaFuncSetAttribute(mcb_fft_kernel,
                         cudaFuncAttributeMaxDynamicSharedMemorySize, (int)smem);
    mcb_fft_kernel<<<B, NTHR, smem>>>(x1, x2, out);
}